// round 1
// baseline (speedup 1.0000x reference)
#include <cuda_runtime.h>
#include <math.h>

#define Bsz  1024
#define INd  1024
#define OUTd 1024
#define NQw  10
#define Gg   4
#define DPT  4
#define QD   1024
#define GQ   4096   // G * QDIM

// ---------------- scratch (device globals: no allocation allowed) ----------
__device__ float g_xq[Bsz * GQ];          // 16 MB
__device__ float g_ang[Bsz * Gg * NQw];   // 160 KB
__device__ float g_probs[Bsz * GQ];       // 16 MB

// ---------------- fp32 NT GEMM: C[m][n] = sum_k A[m][k]*s[k]*B[n][k] + bias[n]
template<int BM,int BN,int BK,int TM,int TN,bool SCALE_A>
__global__ void __launch_bounds__((BM/TM)*(BN/TN))
sgemm_nt(int M,int N,int K,
         const float* __restrict__ A,
         const float* __restrict__ ascale,
         const float* __restrict__ Bm,
         const float* __restrict__ bias,
         float* __restrict__ C)
{
    constexpr int NT = (BM/TM)*(BN/TN);
    __shared__ float As[BK][BM];
    __shared__ float Bs[BK][BN];
    const int tid = threadIdx.x;
    const int nx  = BN/TN;
    const int tx  = tid % nx;
    const int ty  = tid / nx;
    const int m0  = blockIdx.y * BM;
    const int n0  = blockIdx.x * BN;

    float acc[TM][TN];
#pragma unroll
    for (int i=0;i<TM;i++)
#pragma unroll
        for (int j=0;j<TN;j++) acc[i][j] = 0.f;

    for (int k0=0;k0<K;k0+=BK){
        constexpr int AV = BM*BK/4;
#pragma unroll
        for (int v=tid; v<AV; v+=NT){
            int row = v/(BK/4), c4 = v%(BK/4);
            float4 tv = *(const float4*)(A + (size_t)(m0+row)*K + k0 + c4*4);
            if (SCALE_A){
                tv.x *= ascale[k0+c4*4+0];
                tv.y *= ascale[k0+c4*4+1];
                tv.z *= ascale[k0+c4*4+2];
                tv.w *= ascale[k0+c4*4+3];
            }
            As[c4*4+0][row]=tv.x; As[c4*4+1][row]=tv.y;
            As[c4*4+2][row]=tv.z; As[c4*4+3][row]=tv.w;
        }
        constexpr int BV = BN*BK/4;
#pragma unroll
        for (int v=tid; v<BV; v+=NT){
            int row = v/(BK/4), c4 = v%(BK/4);
            float4 tv = *(const float4*)(Bm + (size_t)(n0+row)*K + k0 + c4*4);
            Bs[c4*4+0][row]=tv.x; Bs[c4*4+1][row]=tv.y;
            Bs[c4*4+2][row]=tv.z; Bs[c4*4+3][row]=tv.w;
        }
        __syncthreads();
#pragma unroll
        for (int k=0;k<BK;k++){
            float ar[TM], br[TN];
#pragma unroll
            for (int i=0;i<TM;i+=4){
                float4 tv = *(const float4*)(&As[k][ty*TM+i]);
                ar[i]=tv.x; ar[i+1]=tv.y; ar[i+2]=tv.z; ar[i+3]=tv.w;
            }
#pragma unroll
            for (int j=0;j<TN;j+=4){
                float4 tv = *(const float4*)(&Bs[k][tx*TN+j]);
                br[j]=tv.x; br[j+1]=tv.y; br[j+2]=tv.z; br[j+3]=tv.w;
            }
#pragma unroll
            for (int i=0;i<TM;i++)
#pragma unroll
                for (int j=0;j<TN;j++)
                    acc[i][j] = fmaf(ar[i], br[j], acc[i][j]);
        }
        __syncthreads();
    }
#pragma unroll
    for (int i=0;i<TM;i++){
        int m = m0 + ty*TM + i;
#pragma unroll
        for (int j=0;j<TN;j++){
            int n = n0 + tx*TN + j;
            C[(size_t)m*N + n] = acc[i][j] + bias[n];
        }
    }
}

// ---------------- angles: ang[b, j] = tanh((x*s) . reup_w[j] + reup_b[j]) * pi
__global__ void __launch_bounds__(320)
angles_kernel(const float* __restrict__ x, const float* __restrict__ inp_scale,
              const float* __restrict__ reup_w, const float* __restrict__ reup_b,
              float* __restrict__ ang)
{
    __shared__ float xs[INd];
    int b = blockIdx.x;
    for (int k=threadIdx.x;k<INd;k+=blockDim.x)
        xs[k] = x[(size_t)b*INd + k] * inp_scale[k];
    __syncthreads();
    int warp = threadIdx.x >> 5, lane = threadIdx.x & 31;
#pragma unroll
    for (int q=0;q<4;q++){
        int j = warp*4 + q;            // j in [0,40)
        const float* w = reup_w + (size_t)j*INd;
        float acc = 0.f;
        for (int k=lane;k<INd;k+=32) acc = fmaf(xs[k], w[k], acc);
#pragma unroll
        for (int o=16;o;o>>=1) acc += __shfl_xor_sync(0xffffffffu, acc, o);
        if (lane==0)
            ang[(size_t)b*(Gg*NQw) + j] = tanhf(acc + reup_b[j]) * 3.14159265358979323846f;
    }
}

// ---------------- complex 2x2 helpers ----------------
struct C2 { float re, im; };
__device__ __forceinline__ C2 cmul(C2 a, C2 b){ return {a.re*b.re - a.im*b.im, a.re*b.im + a.im*b.re}; }
__device__ __forceinline__ C2 cadd(C2 a, C2 b){ return {a.re+b.re, a.im+b.im}; }
struct M2 { C2 m00, m01, m10, m11; };
__device__ __forceinline__ M2 mmul(M2 A, M2 B){  // A @ B
    M2 r;
    r.m00 = cadd(cmul(A.m00,B.m00), cmul(A.m01,B.m10));
    r.m01 = cadd(cmul(A.m00,B.m01), cmul(A.m01,B.m11));
    r.m10 = cadd(cmul(A.m10,B.m00), cmul(A.m11,B.m10));
    r.m11 = cadd(cmul(A.m10,B.m01), cmul(A.m11,B.m11));
    return r;
}
__device__ __forceinline__ M2 ry_m(float t){
    float c=cosf(0.5f*t), s=sinf(0.5f*t);
    return {{c,0.f},{-s,0.f},{s,0.f},{c,0.f}};
}
__device__ __forceinline__ M2 rx_m(float t){
    float c=cosf(0.5f*t), s=sinf(0.5f*t);
    return {{c,0.f},{0.f,-s},{0.f,-s},{c,0.f}};
}
__device__ __forceinline__ M2 u3_m(float t,float p,float l){
    float c=cosf(0.5f*t), s=sinf(0.5f*t);
    float cp=cosf(p), sp=sinf(p), cl=cosf(l), sl=sinf(l);
    M2 r;
    r.m00 = {c, 0.f};
    r.m01 = {-cl*s, -sl*s};
    r.m10 = {cp*s, sp*s};
    r.m11 = {(cp*cl - sp*sl)*c, (sp*cl + cp*sl)*c};
    return r;
}

// ---------------- quantum circuit: one block per (b,g) state ---------------
// 5 rounds of 10 fused single-qubit gates; CNOT-ring = index permutation.
__global__ void __launch_bounds__(512)
quantum_kernel(const float* __restrict__ xq, const float* __restrict__ ang,
               const float* __restrict__ qw, const float* __restrict__ us,
               const float* __restrict__ mw, float* __restrict__ probs)
{
    __shared__ float sre[2][QD];
    __shared__ float sim[2][QD];
    __shared__ float gm[NQw][8];
    __shared__ float redbuf[16];

    const int s = blockIdx.x;
    const int b = s >> 2, g = s & 3;
    const int t = threadIdx.x;

    // ---- load xq row, L2-normalize ----
    const float* xrow = xq + (size_t)b*GQ + (size_t)g*QD;
    float v0 = xrow[t], v1 = xrow[t+512];
    float ssum = v0*v0 + v1*v1;
#pragma unroll
    for (int o=16;o;o>>=1) ssum += __shfl_xor_sync(0xffffffffu, ssum, o);
    if ((t & 31) == 0) redbuf[t>>5] = ssum;
    __syncthreads();
    if (t < 16){
        float v = redbuf[t];
#pragma unroll
        for (int o=8;o;o>>=1) v += __shfl_xor_sync(0x0000ffffu, v, o);
        if (t==0) redbuf[0] = v;
    }
    __syncthreads();
    const float inv = 1.0f/(sqrtf(redbuf[0]) + 1e-9f);
    int cur = 0;
    sre[0][t]     = v0*inv;  sre[0][t+512] = v1*inv;
    sim[0][t]     = 0.f;     sim[0][t+512] = 0.f;
    __syncthreads();

    for (int r=0;r<5;r++){
        // ---- build fused per-wire 2x2 matrices (threads 0..9) ----
        if (t < NQw){
            const int i = t;
            M2 M;
            if (r < 4){
                float a = ang[(size_t)b*(Gg*NQw) + g*NQw + i];
                float theta = a * us[(g*DPT + r)*NQw + i];
                if (r > 0) theta += qw[((g*DPT + (r-1))*NQw + i)*3 + 2];
                const float* q = qw + ((size_t)(g*DPT + r)*NQw + i)*3;
                M = mmul(ry_m(q[1]), mmul(rx_m(q[0]), ry_m(theta)));
            } else {
                const float* m = mw + ((size_t)g*NQw + i)*3;
                float t2 = qw[((g*DPT + 3)*NQw + i)*3 + 2];
                M = mmul(u3_m(m[0], m[1], m[2]), ry_m(t2));
            }
            gm[i][0]=M.m00.re; gm[i][1]=M.m00.im;
            gm[i][2]=M.m01.re; gm[i][3]=M.m01.im;
            gm[i][4]=M.m10.re; gm[i][5]=M.m10.im;
            gm[i][6]=M.m11.re; gm[i][7]=M.m11.im;
        }
        __syncthreads();

        // ---- 10 single-qubit gates, one pair per thread ----
#pragma unroll
        for (int i=0;i<NQw;i++){
            const int tb = 9 - i;               // wire i <-> bit (9-i)
            const int low = t & ((1<<tb)-1);
            const int i0 = ((t>>tb)<<(tb+1)) | low;
            const int i1 = i0 | (1<<tb);
            float ar=sre[cur][i0], ai=sim[cur][i0];
            float br=sre[cur][i1], bi=sim[cur][i1];
            float m00r=gm[i][0], m00i=gm[i][1], m01r=gm[i][2], m01i=gm[i][3];
            float m10r=gm[i][4], m10i=gm[i][5], m11r=gm[i][6], m11i=gm[i][7];
            float n0r = m00r*ar - m00i*ai + m01r*br - m01i*bi;
            float n0i = m00r*ai + m00i*ar + m01r*bi + m01i*br;
            float n1r = m10r*ar - m10i*ai + m11r*br - m11i*bi;
            float n1i = m10r*ai + m10i*ar + m11r*bi + m11i*br;
            sre[cur][i0]=n0r; sim[cur][i0]=n0i;
            sre[cur][i1]=n1r; sim[cur][i1]=n1i;
            __syncthreads();
        }

        // ---- CNOT-ring permutation (rounds 0..3) ----
        if (r < 4){
            const int nxt = cur ^ 1;
#pragma unroll
            for (int u=0;u<2;u++){
                int y = t + u*512;
                int z = y;
#pragma unroll
                for (int k=9;k>=0;--k){
                    int cb  = 9 - k;
                    int tb2 = 9 - ((k+1)%10);
                    z ^= ((z>>cb)&1) << tb2;
                }
                sre[nxt][y] = sre[cur][z];
                sim[nxt][y] = sim[cur][z];
            }
            __syncthreads();
            cur = nxt;
        }
    }

    // ---- probabilities ----
    float* prow = probs + (size_t)b*GQ + (size_t)g*QD;
    float r0=sre[cur][t],     i0v=sim[cur][t];
    float r1=sre[cur][t+512], i1v=sim[cur][t+512];
    prow[t]     = r0*r0 + i0v*i0v;
    prow[t+512] = r1*r1 + i1v*i1v;
}

// ---------------- launch ----------------
extern "C" void kernel_launch(void* const* d_in, const int* in_sizes, int n_in,
                              void* d_out, int out_size)
{
    const float* x          = (const float*)d_in[0];
    const float* inp_scale  = (const float*)d_in[1];
    const float* proj_in_w  = (const float*)d_in[2];
    const float* proj_in_b  = (const float*)d_in[3];
    const float* reup_w     = (const float*)d_in[4];
    const float* reup_b     = (const float*)d_in[5];
    const float* q_weights  = (const float*)d_in[6];
    const float* upload_sc  = (const float*)d_in[7];
    const float* meas_w     = (const float*)d_in[8];
    const float* proj_out_w = (const float*)d_in[9];
    const float* proj_out_b = (const float*)d_in[10];
    float* out = (float*)d_out;

    void *pxq, *pang, *pprobs;
    cudaGetSymbolAddress(&pxq,    g_xq);
    cudaGetSymbolAddress(&pang,   g_ang);
    cudaGetSymbolAddress(&pprobs, g_probs);
    float* xq    = (float*)pxq;
    float* angp  = (float*)pang;
    float* probs = (float*)pprobs;

    // GEMM-in: (1024 x 4096) = (x * inp_scale) @ proj_in_w^T + b
    {
        dim3 grid(GQ/64, Bsz/128);
        sgemm_nt<128,64,16,8,4,true><<<grid, 256>>>(
            Bsz, GQ, INd, x, inp_scale, proj_in_w, proj_in_b, xq);
    }
    // angles
    angles_kernel<<<Bsz, 320>>>(x, inp_scale, reup_w, reup_b, angp);

    // quantum circuit: 4096 states
    quantum_kernel<<<Bsz*Gg, 512>>>(xq, angp, q_weights, upload_sc, meas_w, probs);

    // GEMM-out: (1024 x 1024) = probs @ proj_out_w^T + b
    {
        dim3 grid(OUTd/64, Bsz/128);
        sgemm_nt<128,64,16,8,4,false><<<grid, 256>>>(
            Bsz, OUTd, GQ, probs, nullptr, proj_out_w, proj_out_b, out);
    }
}

// round 3
// speedup vs baseline: 1.8084x; 1.8084x over previous
#include <cuda_runtime.h>
#include <cuda_bf16.h>
#include <math.h>
#include <cstdint>

#define Bsz  1024
#define INd  1024
#define OUTd 1024
#define NQw  10
#define Gg   4
#define DPT  4
#define QD   1024
#define GQ   4096   // G * QDIM

// ---------------- scratch (device globals: no allocation allowed) ----------
__device__ float g_xq[Bsz * GQ];            // 16 MB (GEMM-in output, fp32)
__device__ float g_ang[Bsz * Gg * NQw];     // 160 KB
__device__ __nv_bfloat16 g_ph[Bsz * GQ];    // probs hi
__device__ __nv_bfloat16 g_pl[Bsz * GQ];    // probs lo
__device__ __nv_bfloat16 g_xh[Bsz * INd];   // (x*scale) hi
__device__ __nv_bfloat16 g_xl[Bsz * INd];
__device__ __nv_bfloat16 g_wih[GQ * INd];   // proj_in_w hi/lo
__device__ __nv_bfloat16 g_wil[GQ * INd];
__device__ __nv_bfloat16 g_woh[OUTd * GQ];  // proj_out_w hi/lo
__device__ __nv_bfloat16 g_wol[OUTd * GQ];

// ================= small PTX helpers (family-stable only; NO tcgen05) ======
__device__ __forceinline__ uint32_t smem_u32(const void* p){
    uint32_t a;
    asm("{ .reg .u64 t; cvta.to.shared.u64 t, %1; cvt.u32.u64 %0, t; }" : "=r"(a) : "l"(p));
    return a;
}
__device__ __forceinline__ void cp16(uint32_t s, const void* g){
    asm volatile("cp.async.cg.shared.global [%0], [%1], 16;" :: "r"(s), "l"(g) : "memory");
}
__device__ __forceinline__ uint32_t lds32(uint32_t a){
    uint32_t v;
    asm volatile("ld.shared.b32 %0, [%1];" : "=r"(v) : "r"(a));
    return v;
}
__device__ __forceinline__ void mma_bf16(float* c, const uint32_t* a, const uint32_t* b){
    asm volatile(
        "mma.sync.aligned.m16n8k16.row.col.f32.bf16.bf16.f32 "
        "{%0,%1,%2,%3}, {%4,%5,%6,%7}, {%8,%9}, {%0,%1,%2,%3};"
        : "+f"(c[0]), "+f"(c[1]), "+f"(c[2]), "+f"(c[3])
        : "r"(a[0]), "r"(a[1]), "r"(a[2]), "r"(a[3]), "r"(b[0]), "r"(b[1]));
}

// ================= bf16 split (hi + lo) converts =================
__global__ void __launch_bounds__(256)
split_bf16(const float* __restrict__ src, const float* __restrict__ scale,
           __nv_bfloat16* __restrict__ hi, __nv_bfloat16* __restrict__ lo, int n)
{
    int i = blockIdx.x * 256 + threadIdx.x;
    if (i < n){
        float v = src[i];
        if (scale) v *= scale[i & (INd - 1)];
        __nv_bfloat16 h = __float2bfloat16(v);
        hi[i] = h;
        lo[i] = __float2bfloat16(v - __bfloat162float(h));
    }
}

// ================= HMMA GEMM: C[M,N] = Ahl[M,K] @ Bhl[N,K]^T + bias ========
// bf16x3 split: Ahi*Bhi + Ahi*Blo + Alo*Bhi, fp32 accum.
// CTA tile 128 x BN, BK=32, 8 warps, warp tile 32 x (BN/2).
// SMEM rows padded to 40 bf16 (80B) -> conflict-free 32-bit fragment loads.
template<int BN>
__global__ void __launch_bounds__(256)
mma_gemm(int M, int N, int K,
         const __nv_bfloat16* __restrict__ Ahi, const __nv_bfloat16* __restrict__ Alo,
         const __nv_bfloat16* __restrict__ Bhi, const __nv_bfloat16* __restrict__ Blo,
         const float* __restrict__ bias, float* __restrict__ C)
{
    constexpr int A_BY = 128 * 80;        // 128 rows x 80B
    constexpr int B_BY = BN * 80;
    constexpr int STG_ = 2 * A_BY + 2 * B_BY;
    constexpr int NT   = BN / 16;         // n8 tiles per warp
    extern __shared__ char smc[];

    const int tid  = threadIdx.x;
    const int wid  = tid >> 5, lane = tid & 31;
    const int grp  = lane >> 2, tig = lane & 3;
    const int wm   = wid & 3,  wn = wid >> 2;
    const int m0   = blockIdx.y * 128, n0 = blockIdx.x * BN;
    const uint32_t sb = smem_u32(smc);

    float c[2][NT][4];
#pragma unroll
    for (int mt = 0; mt < 2; mt++)
#pragma unroll
        for (int nt = 0; nt < NT; nt++)
#pragma unroll
            for (int q = 0; q < 4; q++) c[mt][nt][q] = 0.f;

    const int nk = K >> 5;

    auto do_prefetch = [&](int i){
        const int st = i & 1;
        const int k0 = i << 5;
        const uint32_t ba = sb + st * STG_;
#pragma unroll
        for (int v = tid; v < 512; v += 256){
            int r = v >> 2, ch = v & 3;
            uint32_t so = ba + r * 80 + ch * 16;
            cp16(so,        Ahi + (size_t)(m0 + r) * K + k0 + ch * 8);
            cp16(so + A_BY, Alo + (size_t)(m0 + r) * K + k0 + ch * 8);
        }
#pragma unroll
        for (int v = tid; v < BN * 4; v += 256){
            int r = v >> 2, ch = v & 3;
            uint32_t so = ba + 2 * A_BY + r * 80 + ch * 16;
            cp16(so,        Bhi + (size_t)(n0 + r) * K + k0 + ch * 8);
            cp16(so + B_BY, Blo + (size_t)(n0 + r) * K + k0 + ch * 8);
        }
        asm volatile("cp.async.commit_group;" ::: "memory");
    };

    do_prefetch(0);
    do_prefetch(1);

    for (int i = 0; i < nk; i++){
        if (i + 2 <= nk) asm volatile("cp.async.wait_group 1;" ::: "memory");
        else             asm volatile("cp.async.wait_group 0;" ::: "memory");
        __syncthreads();

        const uint32_t ba = sb + (i & 1) * STG_;
        const uint32_t bb = ba + 2 * A_BY;

#pragma unroll
        for (int kk = 0; kk < 2; kk++){
            uint32_t ah[2][4], al[2][4];
#pragma unroll
            for (int mt = 0; mt < 2; mt++){
                const int r0 = wm * 32 + mt * 16 + grp;
                const uint32_t o00 = ba + (r0    ) * 80 + kk * 32 + tig * 4;
                const uint32_t o10 = ba + (r0 + 8) * 80 + kk * 32 + tig * 4;
                ah[mt][0] = lds32(o00);        ah[mt][1] = lds32(o10);
                ah[mt][2] = lds32(o00 + 16);   ah[mt][3] = lds32(o10 + 16);
                al[mt][0] = lds32(o00 + A_BY);      al[mt][1] = lds32(o10 + A_BY);
                al[mt][2] = lds32(o00 + A_BY + 16); al[mt][3] = lds32(o10 + A_BY + 16);
            }
            uint32_t bh[NT][2], bl[NT][2];
#pragma unroll
            for (int nt = 0; nt < NT; nt++){
                const int n = wn * (NT * 8) + nt * 8 + grp;
                const uint32_t o = bb + n * 80 + kk * 32 + tig * 4;
                bh[nt][0] = lds32(o);          bh[nt][1] = lds32(o + 16);
                bl[nt][0] = lds32(o + B_BY);   bl[nt][1] = lds32(o + B_BY + 16);
            }
#pragma unroll
            for (int mt = 0; mt < 2; mt++)
#pragma unroll
                for (int nt = 0; nt < NT; nt++){
                    mma_bf16(c[mt][nt], ah[mt], bh[nt]);
                    mma_bf16(c[mt][nt], ah[mt], bl[nt]);
                    mma_bf16(c[mt][nt], al[mt], bh[nt]);
                }
        }
        __syncthreads();
        if (i + 2 < nk) do_prefetch(i + 2);
    }

    // epilogue
#pragma unroll
    for (int mt = 0; mt < 2; mt++){
        const int row0 = m0 + wm * 32 + mt * 16 + grp;
#pragma unroll
        for (int nt = 0; nt < NT; nt++){
            const int col = n0 + wn * (NT * 8) + nt * 8 + 2 * tig;
            const float b0 = bias[col], b1 = bias[col + 1];
            float2 v0 = make_float2(c[mt][nt][0] + b0, c[mt][nt][1] + b1);
            float2 v1 = make_float2(c[mt][nt][2] + b0, c[mt][nt][3] + b1);
            *(float2*)&C[(size_t)row0       * N + col] = v0;
            *(float2*)&C[(size_t)(row0 + 8) * N + col] = v1;
        }
    }
}

// ---------------- angles: ang[b, j] = tanh((x*s) . reup_w[j] + reup_b[j]) * pi
__global__ void __launch_bounds__(320)
angles_kernel(const float* __restrict__ x, const float* __restrict__ inp_scale,
              const float* __restrict__ reup_w, const float* __restrict__ reup_b,
              float* __restrict__ ang)
{
    __shared__ float xs[INd];
    int b = blockIdx.x;
    for (int k = threadIdx.x; k < INd; k += blockDim.x)
        xs[k] = x[(size_t)b * INd + k] * inp_scale[k];
    __syncthreads();
    int warp = threadIdx.x >> 5, lane = threadIdx.x & 31;
#pragma unroll
    for (int q = 0; q < 4; q++){
        int j = warp * 4 + q;            // j in [0,40)
        const float* w = reup_w + (size_t)j * INd;
        float acc = 0.f;
        for (int k = lane; k < INd; k += 32) acc = fmaf(xs[k], w[k], acc);
#pragma unroll
        for (int o = 16; o; o >>= 1) acc += __shfl_xor_sync(0xffffffffu, acc, o);
        if (lane == 0)
            ang[(size_t)b * (Gg * NQw) + j] = tanhf(acc + reup_b[j]) * 3.14159265358979323846f;
    }
}

// ---------------- complex 2x2 helpers ----------------
struct C2 { float re, im; };
__device__ __forceinline__ C2 cmul(C2 a, C2 b){ return {a.re*b.re - a.im*b.im, a.re*b.im + a.im*b.re}; }
__device__ __forceinline__ C2 cadd(C2 a, C2 b){ return {a.re+b.re, a.im+b.im}; }
struct M2 { C2 m00, m01, m10, m11; };
__device__ __forceinline__ M2 mmul(M2 A, M2 B){  // A @ B
    M2 r;
    r.m00 = cadd(cmul(A.m00,B.m00), cmul(A.m01,B.m10));
    r.m01 = cadd(cmul(A.m00,B.m01), cmul(A.m01,B.m11));
    r.m10 = cadd(cmul(A.m10,B.m00), cmul(A.m11,B.m10));
    r.m11 = cadd(cmul(A.m10,B.m01), cmul(A.m11,B.m11));
    return r;
}
__device__ __forceinline__ M2 ry_m(float t){
    float c=cosf(0.5f*t), s=sinf(0.5f*t);
    return {{c,0.f},{-s,0.f},{s,0.f},{c,0.f}};
}
__device__ __forceinline__ M2 rx_m(float t){
    float c=cosf(0.5f*t), s=sinf(0.5f*t);
    return {{c,0.f},{0.f,-s},{0.f,-s},{c,0.f}};
}
__device__ __forceinline__ M2 u3_m(float t,float p,float l){
    float c=cosf(0.5f*t), s=sinf(0.5f*t);
    float cp=cosf(p), sp=sinf(p), cl=cosf(l), sl=sinf(l);
    M2 r;
    r.m00 = {c, 0.f};
    r.m01 = {-cl*s, -sl*s};
    r.m10 = {cp*s, sp*s};
    r.m11 = {(cp*cl - sp*sl)*c, (sp*cl + cp*sl)*c};
    return r;
}

// ---------------- quantum circuit: one block per (b,g) state ---------------
// 5 rounds of 10 fused single-qubit gates; CNOT-ring = index permutation.
__global__ void __launch_bounds__(512)
quantum_kernel(const float* __restrict__ xq, const float* __restrict__ ang,
               const float* __restrict__ qw, const float* __restrict__ us,
               const float* __restrict__ mw,
               __nv_bfloat16* __restrict__ ph, __nv_bfloat16* __restrict__ pl)
{
    __shared__ float sre[2][QD];
    __shared__ float sim[2][QD];
    __shared__ float gm[NQw][8];
    __shared__ float redbuf[16];

    const int s = blockIdx.x;
    const int b = s >> 2, g = s & 3;
    const int t = threadIdx.x;

    // ---- load xq row, L2-normalize ----
    const float* xrow = xq + (size_t)b*GQ + (size_t)g*QD;
    float v0 = xrow[t], v1 = xrow[t+512];
    float ssum = v0*v0 + v1*v1;
#pragma unroll
    for (int o=16;o;o>>=1) ssum += __shfl_xor_sync(0xffffffffu, ssum, o);
    if ((t & 31) == 0) redbuf[t>>5] = ssum;
    __syncthreads();
    if (t < 16){
        float v = redbuf[t];
#pragma unroll
        for (int o=8;o;o>>=1) v += __shfl_xor_sync(0x0000ffffu, v, o);
        if (t==0) redbuf[0] = v;
    }
    __syncthreads();
    const float inv = 1.0f/(sqrtf(redbuf[0]) + 1e-9f);
    int cur = 0;
    sre[0][t]     = v0*inv;  sre[0][t+512] = v1*inv;
    sim[0][t]     = 0.f;     sim[0][t+512] = 0.f;
    __syncthreads();

    for (int r=0;r<5;r++){
        // ---- build fused per-wire 2x2 matrices (threads 0..9) ----
        if (t < NQw){
            const int i = t;
            M2 M;
            if (r < 4){
                float a = ang[(size_t)b*(Gg*NQw) + g*NQw + i];
                float theta = a * us[(g*DPT + r)*NQw + i];
                if (r > 0) theta += qw[((g*DPT + (r-1))*NQw + i)*3 + 2];
                const float* q = qw + ((size_t)(g*DPT + r)*NQw + i)*3;
                M = mmul(ry_m(q[1]), mmul(rx_m(q[0]), ry_m(theta)));
            } else {
                const float* m = mw + ((size_t)g*NQw + i)*3;
                float t2 = qw[((g*DPT + 3)*NQw + i)*3 + 2];
                M = mmul(u3_m(m[0], m[1], m[2]), ry_m(t2));
            }
            gm[i][0]=M.m00.re; gm[i][1]=M.m00.im;
            gm[i][2]=M.m01.re; gm[i][3]=M.m01.im;
            gm[i][4]=M.m10.re; gm[i][5]=M.m10.im;
            gm[i][6]=M.m11.re; gm[i][7]=M.m11.im;
        }
        __syncthreads();

        // ---- 10 single-qubit gates, one pair per thread ----
#pragma unroll
        for (int i=0;i<NQw;i++){
            const int tb = 9 - i;               // wire i <-> bit (9-i)
            const int low = t & ((1<<tb)-1);
            const int i0 = ((t>>tb)<<(tb+1)) | low;
            const int i1 = i0 | (1<<tb);
            float ar=sre[cur][i0], ai=sim[cur][i0];
            float br=sre[cur][i1], bi=sim[cur][i1];
            float m00r=gm[i][0], m00i=gm[i][1], m01r=gm[i][2], m01i=gm[i][3];
            float m10r=gm[i][4], m10i=gm[i][5], m11r=gm[i][6], m11i=gm[i][7];
            float n0r = m00r*ar - m00i*ai + m01r*br - m01i*bi;
            float n0i = m00r*ai + m00i*ar + m01r*bi + m01i*br;
            float n1r = m10r*ar - m10i*ai + m11r*br - m11i*bi;
            float n1i = m10r*ai + m10i*ar + m11r*bi + m11i*br;
            sre[cur][i0]=n0r; sim[cur][i0]=n0i;
            sre[cur][i1]=n1r; sim[cur][i1]=n1i;
            __syncthreads();
        }

        // ---- CNOT-ring permutation (rounds 0..3) ----
        if (r < 4){
            const int nxt = cur ^ 1;
#pragma unroll
            for (int u=0;u<2;u++){
                int y = t + u*512;
                int z = y;
#pragma unroll
                for (int k=9;k>=0;--k){
                    int cb  = 9 - k;
                    int tb2 = 9 - ((k+1)%10);
                    z ^= ((z>>cb)&1) << tb2;
                }
                sre[nxt][y] = sre[cur][z];
                sim[nxt][y] = sim[cur][z];
            }
            __syncthreads();
            cur = nxt;
        }
    }

    // ---- probabilities -> bf16 hi/lo split ----
    size_t o = (size_t)b*GQ + (size_t)g*QD;
    float p0 = sre[cur][t]*sre[cur][t] + sim[cur][t]*sim[cur][t];
    float p1 = sre[cur][t+512]*sre[cur][t+512] + sim[cur][t+512]*sim[cur][t+512];
    __nv_bfloat16 h0 = __float2bfloat16(p0);
    __nv_bfloat16 h1 = __float2bfloat16(p1);
    ph[o+t]     = h0;  pl[o+t]     = __float2bfloat16(p0 - __bfloat162float(h0));
    ph[o+t+512] = h1;  pl[o+t+512] = __float2bfloat16(p1 - __bfloat162float(h1));
}

// ---------------- launch ----------------
extern "C" void kernel_launch(void* const* d_in, const int* in_sizes, int n_in,
                              void* d_out, int out_size)
{
    const float* x          = (const float*)d_in[0];
    const float* inp_scale  = (const float*)d_in[1];
    const float* proj_in_w  = (const float*)d_in[2];
    const float* proj_in_b  = (const float*)d_in[3];
    const float* reup_w     = (const float*)d_in[4];
    const float* reup_b     = (const float*)d_in[5];
    const float* q_weights  = (const float*)d_in[6];
    const float* upload_sc  = (const float*)d_in[7];
    const float* meas_w     = (const float*)d_in[8];
    const float* proj_out_w = (const float*)d_in[9];
    const float* proj_out_b = (const float*)d_in[10];
    float* out = (float*)d_out;

    void *pxq, *pang, *pph, *ppl, *pxh, *pxl, *pwih, *pwil, *pwoh, *pwol;
    cudaGetSymbolAddress(&pxq,  g_xq);
    cudaGetSymbolAddress(&pang, g_ang);
    cudaGetSymbolAddress(&pph,  g_ph);
    cudaGetSymbolAddress(&ppl,  g_pl);
    cudaGetSymbolAddress(&pxh,  g_xh);
    cudaGetSymbolAddress(&pxl,  g_xl);
    cudaGetSymbolAddress(&pwih, g_wih);
    cudaGetSymbolAddress(&pwil, g_wil);
    cudaGetSymbolAddress(&pwoh, g_woh);
    cudaGetSymbolAddress(&pwol, g_wol);

    // dynamic SMEM: BN=128 -> 2*(2*10240+2*10240)=81920; BN=64 -> 61440
    cudaFuncSetAttribute(mma_gemm<128>, cudaFuncAttributeMaxDynamicSharedMemorySize, 81920);
    cudaFuncSetAttribute(mma_gemm<64>,  cudaFuncAttributeMaxDynamicSharedMemorySize, 61440);

    // bf16 hi/lo splits
    split_bf16<<<(Bsz*INd + 255)/256, 256>>>(x, inp_scale,
        (__nv_bfloat16*)pxh, (__nv_bfloat16*)pxl, Bsz*INd);
    split_bf16<<<(GQ*INd + 255)/256, 256>>>(proj_in_w, nullptr,
        (__nv_bfloat16*)pwih, (__nv_bfloat16*)pwil, GQ*INd);
    split_bf16<<<(OUTd*GQ + 255)/256, 256>>>(proj_out_w, nullptr,
        (__nv_bfloat16*)pwoh, (__nv_bfloat16*)pwol, OUTd*GQ);

    // GEMM-in: xq[1024, 4096] = (x*scale) @ proj_in_w^T + b
    {
        dim3 grid(GQ/128, Bsz/128);
        mma_gemm<128><<<grid, 256, 81920>>>(Bsz, GQ, INd,
            (const __nv_bfloat16*)pxh, (const __nv_bfloat16*)pxl,
            (const __nv_bfloat16*)pwih, (const __nv_bfloat16*)pwil,
            proj_in_b, (float*)pxq);
    }

    // angles
    angles_kernel<<<Bsz, 320>>>(x, inp_scale, reup_w, reup_b, (float*)pang);

    // quantum circuit: 4096 states -> probs (bf16 hi/lo)
    quantum_kernel<<<Bsz*Gg, 512>>>((const float*)pxq, (const float*)pang,
        q_weights, upload_sc, meas_w,
        (__nv_bfloat16*)pph, (__nv_bfloat16*)ppl);

    // GEMM-out: out[1024, 1024] = probs @ proj_out_w^T + b
    {
        dim3 grid(OUTd/64, Bsz/128);
        mma_gemm<64><<<grid, 256, 61440>>>(Bsz, OUTd, GQ,
            (const __nv_bfloat16*)pph, (const __nv_bfloat16*)ppl,
            (const __nv_bfloat16*)pwoh, (const __nv_bfloat16*)pwol,
            proj_out_b, out);
    }
}

// round 4
// speedup vs baseline: 2.4139x; 1.3348x over previous
#include <cuda_runtime.h>
#include <cuda_bf16.h>
#include <math.h>
#include <cstdint>

#define Bsz  1024
#define INd  1024
#define OUTd 1024
#define NQw  10
#define Gg   4
#define DPT  4
#define QD   1024
#define GQ   4096   // G * QDIM

// ---------------- scratch (device globals: no allocation allowed) ----------
__device__ float g_xq[Bsz * GQ];            // 16 MB (GEMM-in output, fp32)
__device__ float g_ang[Bsz * Gg * NQw];     // 160 KB
__device__ __nv_bfloat16 g_ph[Bsz * GQ];    // probs hi
__device__ __nv_bfloat16 g_pl[Bsz * GQ];    // probs lo
__device__ __nv_bfloat16 g_xh[Bsz * INd];   // (x*scale) hi
__device__ __nv_bfloat16 g_xl[Bsz * INd];
__device__ __nv_bfloat16 g_wih[GQ * INd];   // proj_in_w hi/lo
__device__ __nv_bfloat16 g_wil[GQ * INd];
__device__ __nv_bfloat16 g_woh[OUTd * GQ];  // proj_out_w hi/lo
__device__ __nv_bfloat16 g_wol[OUTd * GQ];

// ================= small PTX helpers (family-stable only; NO tcgen05) ======
__device__ __forceinline__ uint32_t smem_u32(const void* p){
    uint32_t a;
    asm("{ .reg .u64 t; cvta.to.shared.u64 t, %1; cvt.u32.u64 %0, t; }" : "=r"(a) : "l"(p));
    return a;
}
__device__ __forceinline__ void cp16(uint32_t s, const void* g){
    asm volatile("cp.async.cg.shared.global [%0], [%1], 16;" :: "r"(s), "l"(g) : "memory");
}
__device__ __forceinline__ void ldm4(uint32_t* r, uint32_t addr){
    asm volatile("ldmatrix.sync.aligned.m8n8.x4.shared.b16 {%0,%1,%2,%3}, [%4];"
                 : "=r"(r[0]), "=r"(r[1]), "=r"(r[2]), "=r"(r[3]) : "r"(addr));
}
__device__ __forceinline__ void mma_bf16(float* c, const uint32_t* a, const uint32_t* b){
    asm volatile(
        "mma.sync.aligned.m16n8k16.row.col.f32.bf16.bf16.f32 "
        "{%0,%1,%2,%3}, {%4,%5,%6,%7}, {%8,%9}, {%0,%1,%2,%3};"
        : "+f"(c[0]), "+f"(c[1]), "+f"(c[2]), "+f"(c[3])
        : "r"(a[0]), "r"(a[1]), "r"(a[2]), "r"(a[3]), "r"(b[0]), "r"(b[1]));
}

// ================= bf16 split (hi + lo) converts =================
__global__ void __launch_bounds__(256)
split_bf16(const float* __restrict__ src, const float* __restrict__ scale,
           __nv_bfloat16* __restrict__ hi, __nv_bfloat16* __restrict__ lo, int n)
{
    int i = blockIdx.x * 256 + threadIdx.x;
    if (i < n){
        float v = src[i];
        if (scale) v *= scale[i & (INd - 1)];
        __nv_bfloat16 h = __float2bfloat16(v);
        hi[i] = h;
        lo[i] = __float2bfloat16(v - __bfloat162float(h));
    }
}

// ================= HMMA GEMM: C[M,N] = Ahl[M,K] @ Bhl[N,K]^T + bias ========
// bf16x3 split: Ahi*Bhi + Ahi*Blo + Alo*Bhi, fp32 accum.
// CTA tile 128 x BN, BK=32, 8 warps, warp tile 32 x (BN/2).
// SMEM rows padded to 40 bf16 (80B); ldmatrix phases hit all 32 banks.
template<int BN>
__global__ void __launch_bounds__(256)
mma_gemm(int M, int N, int K,
         const __nv_bfloat16* __restrict__ Ahi, const __nv_bfloat16* __restrict__ Alo,
         const __nv_bfloat16* __restrict__ Bhi, const __nv_bfloat16* __restrict__ Blo,
         const float* __restrict__ bias, float* __restrict__ C)
{
    constexpr int A_BY = 128 * 80;        // 128 rows x 80B
    constexpr int B_BY = BN * 80;
    constexpr int STG_ = 2 * A_BY + 2 * B_BY;
    constexpr int NT   = BN / 16;         // n8 tiles per warp
    extern __shared__ char smc[];

    const int tid  = threadIdx.x;
    const int wid  = tid >> 5, lane = tid & 31;
    const int grp  = lane >> 2, tig = lane & 3;
    const int wm   = wid & 3,  wn = wid >> 2;
    const int m0   = blockIdx.y * 128, n0 = blockIdx.x * BN;
    const uint32_t sb = smem_u32(smc);

    // ldmatrix lane-address components
    const int a_row = lane & 15, a_off = (lane >> 4) << 4;          // A .x4
    const int b_row = ((lane >> 4) << 3) + (lane & 7);              // B .x4 (2 tiles)
    const int b_off = ((lane >> 3) & 1) << 4;

    float c[2][NT][4];
#pragma unroll
    for (int mt = 0; mt < 2; mt++)
#pragma unroll
        for (int nt = 0; nt < NT; nt++)
#pragma unroll
            for (int q = 0; q < 4; q++) c[mt][nt][q] = 0.f;

    const int nk = K >> 5;

    auto do_prefetch = [&](int i){
        const int st = i & 1;
        const int k0 = i << 5;
        const uint32_t ba = sb + st * STG_;
#pragma unroll
        for (int v = tid; v < 512; v += 256){
            int r = v >> 2, ch = v & 3;
            uint32_t so = ba + r * 80 + ch * 16;
            cp16(so,        Ahi + (size_t)(m0 + r) * K + k0 + ch * 8);
            cp16(so + A_BY, Alo + (size_t)(m0 + r) * K + k0 + ch * 8);
        }
#pragma unroll
        for (int v = tid; v < BN * 4; v += 256){
            int r = v >> 2, ch = v & 3;
            uint32_t so = ba + 2 * A_BY + r * 80 + ch * 16;
            cp16(so,        Bhi + (size_t)(n0 + r) * K + k0 + ch * 8);
            cp16(so + B_BY, Blo + (size_t)(n0 + r) * K + k0 + ch * 8);
        }
        asm volatile("cp.async.commit_group;" ::: "memory");
    };

    do_prefetch(0);
    do_prefetch(1);

    for (int i = 0; i < nk; i++){
        if (i + 2 <= nk) asm volatile("cp.async.wait_group 1;" ::: "memory");
        else             asm volatile("cp.async.wait_group 0;" ::: "memory");
        __syncthreads();

        const uint32_t ba = sb + (i & 1) * STG_;
        const uint32_t bb = ba + 2 * A_BY;

#pragma unroll
        for (int kk = 0; kk < 2; kk++){
            uint32_t ah[2][4], al[2][4];
#pragma unroll
            for (int mt = 0; mt < 2; mt++){
                const uint32_t oa = ba + (wm * 32 + mt * 16 + a_row) * 80 + kk * 32 + a_off;
                ldm4(ah[mt], oa);
                ldm4(al[mt], oa + A_BY);
            }
            uint32_t bh[NT][2], bl[NT][2];
#pragma unroll
            for (int np = 0; np < NT / 2; np++){
                const uint32_t ob = bb + (wn * (NT * 8) + np * 16 + b_row) * 80 + kk * 32 + b_off;
                uint32_t t4[4];
                ldm4(t4, ob);
                bh[2*np][0] = t4[0]; bh[2*np][1] = t4[1];
                bh[2*np+1][0] = t4[2]; bh[2*np+1][1] = t4[3];
                ldm4(t4, ob + B_BY);
                bl[2*np][0] = t4[0]; bl[2*np][1] = t4[1];
                bl[2*np+1][0] = t4[2]; bl[2*np+1][1] = t4[3];
            }
#pragma unroll
            for (int mt = 0; mt < 2; mt++)
#pragma unroll
                for (int nt = 0; nt < NT; nt++){
                    mma_bf16(c[mt][nt], ah[mt], bh[nt]);
                    mma_bf16(c[mt][nt], ah[mt], bl[nt]);
                    mma_bf16(c[mt][nt], al[mt], bh[nt]);
                }
        }
        __syncthreads();
        if (i + 2 < nk) do_prefetch(i + 2);
    }

    // epilogue
#pragma unroll
    for (int mt = 0; mt < 2; mt++){
        const int row0 = m0 + wm * 32 + mt * 16 + grp;
#pragma unroll
        for (int nt = 0; nt < NT; nt++){
            const int col = n0 + wn * (NT * 8) + nt * 8 + 2 * tig;
            const float b0 = bias[col], b1 = bias[col + 1];
            float2 v0 = make_float2(c[mt][nt][0] + b0, c[mt][nt][1] + b1);
            float2 v1 = make_float2(c[mt][nt][2] + b0, c[mt][nt][3] + b1);
            *(float2*)&C[(size_t)row0       * N + col] = v0;
            *(float2*)&C[(size_t)(row0 + 8) * N + col] = v1;
        }
    }
}

// ---------------- angles: ang[b, j] = tanh((x*s) . reup_w[j] + reup_b[j]) * pi
__global__ void __launch_bounds__(320)
angles_kernel(const float* __restrict__ x, const float* __restrict__ inp_scale,
              const float* __restrict__ reup_w, const float* __restrict__ reup_b,
              float* __restrict__ ang)
{
    __shared__ float xs[INd];
    int b = blockIdx.x;
    for (int k = threadIdx.x; k < INd; k += blockDim.x)
        xs[k] = x[(size_t)b * INd + k] * inp_scale[k];
    __syncthreads();
    int warp = threadIdx.x >> 5, lane = threadIdx.x & 31;
#pragma unroll
    for (int q = 0; q < 4; q++){
        int j = warp * 4 + q;            // j in [0,40)
        const float* w = reup_w + (size_t)j * INd;
        float acc = 0.f;
        for (int k = lane; k < INd; k += 32) acc = fmaf(xs[k], w[k], acc);
#pragma unroll
        for (int o = 16; o; o >>= 1) acc += __shfl_xor_sync(0xffffffffu, acc, o);
        if (lane == 0)
            ang[(size_t)b * (Gg * NQw) + j] = tanhf(acc + reup_b[j]) * 3.14159265358979323846f;
    }
}

// ---------------- complex 2x2 helpers ----------------
struct C2 { float re, im; };
__device__ __forceinline__ C2 cmul(C2 a, C2 b){ return {a.re*b.re - a.im*b.im, a.re*b.im + a.im*b.re}; }
__device__ __forceinline__ C2 cadd(C2 a, C2 b){ return {a.re+b.re, a.im+b.im}; }
struct M2 { C2 m00, m01, m10, m11; };
__device__ __forceinline__ M2 mmul(M2 A, M2 B){  // A @ B
    M2 r;
    r.m00 = cadd(cmul(A.m00,B.m00), cmul(A.m01,B.m10));
    r.m01 = cadd(cmul(A.m00,B.m01), cmul(A.m01,B.m11));
    r.m10 = cadd(cmul(A.m10,B.m00), cmul(A.m11,B.m10));
    r.m11 = cadd(cmul(A.m10,B.m01), cmul(A.m11,B.m11));
    return r;
}
__device__ __forceinline__ M2 ry_m(float t){
    float c=cosf(0.5f*t), s=sinf(0.5f*t);
    return {{c,0.f},{-s,0.f},{s,0.f},{c,0.f}};
}
__device__ __forceinline__ M2 rx_m(float t){
    float c=cosf(0.5f*t), s=sinf(0.5f*t);
    return {{c,0.f},{0.f,-s},{0.f,-s},{c,0.f}};
}
__device__ __forceinline__ M2 u3_m(float t,float p,float l){
    float c=cosf(0.5f*t), s=sinf(0.5f*t);
    float cp=cosf(p), sp=sinf(p), cl=cosf(l), sl=sinf(l);
    M2 r;
    r.m00 = {c, 0.f};
    r.m01 = {-cl*s, -sl*s};
    r.m10 = {cp*s, sp*s};
    r.m11 = {(cp*cl - sp*sl)*c, (sp*cl + cp*sl)*c};
    return r;
}

// ================= quantum circuit: one WARP per (b,g) state ===============
// State register-resident: lane l holds amps z with bits[9:5]=l (32 per lane).
// Wires 0-4 -> lane-bit butterflies via shfl_xor; wires 5-9 -> in-register.
// CNOT-ring = index permutation, done via padded SMEM bounce (4x per circuit).
template<int SB>
__device__ __forceinline__ void gate_in(float* sr, float* si,
    float c00r, float c00i, float c01r, float c01i,
    float c10r, float c10i, float c11r, float c11i)
{
#pragma unroll
    for (int jj = 0; jj < 16; jj++){
        const int j0 = ((jj >> SB) << (SB + 1)) | (jj & ((1 << SB) - 1));
        const int j1 = j0 | (1 << SB);
        float ar = sr[j0], ai = si[j0], br = sr[j1], bi = si[j1];
        sr[j0] = c00r*ar - c00i*ai + c01r*br - c01i*bi;
        si[j0] = c00r*ai + c00i*ar + c01r*bi + c01i*br;
        sr[j1] = c10r*ar - c10i*ai + c11r*br - c11i*bi;
        si[j1] = c10r*ai + c10i*ar + c11r*bi + c11i*br;
    }
}

__global__ void __launch_bounds__(128)
quantum_reg(const float* __restrict__ xq, const float* __restrict__ ang,
            const float* __restrict__ qw, const float* __restrict__ us,
            const float* __restrict__ mw,
            __nv_bfloat16* __restrict__ ph, __nv_bfloat16* __restrict__ pl)
{
    __shared__ float ss[4][33 * 32];    // per-warp padded bounce buffer
    const int wid = threadIdx.x >> 5, l = threadIdx.x & 31;
    const int s = blockIdx.x * 4 + wid;
    const int b = s >> 2, g = s & 3;
    const unsigned FULL = 0xffffffffu;
    float* buf = ss[wid];

    // ---- coalesced load + L2-normalize into registers ----
    const float* xrow = xq + (size_t)b * GQ + (size_t)g * QD;
#pragma unroll
    for (int j = 0; j < 32; j++) buf[j * 33 + l] = xrow[j * 32 + l];
    __syncwarp();
    float sr[32], si[32];
    float nrm = 0.f;
#pragma unroll
    for (int j = 0; j < 32; j++){
        sr[j] = buf[l * 33 + j];
        nrm = fmaf(sr[j], sr[j], nrm);
        si[j] = 0.f;
    }
#pragma unroll
    for (int o = 16; o; o >>= 1) nrm += __shfl_xor_sync(FULL, nrm, o);
    const float inv = 1.0f / (sqrtf(nrm) + 1e-9f);
#pragma unroll
    for (int j = 0; j < 32; j++) sr[j] *= inv;
    __syncwarp();

    for (int r = 0; r < 5; r++){
        // ---- lanes 0..9 build fused 2x2 gate matrix for wire l ----
        float m0=0,m1=0,m2=0,m3=0,m4=0,m5=0,m6=0,m7=0;
        if (l < NQw){
            const int i = l;
            M2 M;
            if (r < 4){
                float a = ang[(size_t)b * (Gg * NQw) + g * NQw + i];
                float theta = a * us[(g * DPT + r) * NQw + i];
                if (r > 0) theta += qw[((g * DPT + (r - 1)) * NQw + i) * 3 + 2];
                const float* q = qw + ((size_t)(g * DPT + r) * NQw + i) * 3;
                M = mmul(ry_m(q[1]), mmul(rx_m(q[0]), ry_m(theta)));
            } else {
                const float* m = mw + ((size_t)g * NQw + i) * 3;
                float t2 = qw[((g * DPT + 3) * NQw + i) * 3 + 2];
                M = mmul(u3_m(m[0], m[1], m[2]), ry_m(t2));
            }
            m0=M.m00.re; m1=M.m00.im; m2=M.m01.re; m3=M.m01.im;
            m4=M.m10.re; m5=M.m10.im; m6=M.m11.re; m7=M.m11.im;
        }

        // ---- wires 0..4: cross-lane butterflies (lane bit 4-i) ----
        for (int i = 0; i < 5; i++){
            float c00r=__shfl_sync(FULL,m0,i), c00i=__shfl_sync(FULL,m1,i);
            float c01r=__shfl_sync(FULL,m2,i), c01i=__shfl_sync(FULL,m3,i);
            float c10r=__shfl_sync(FULL,m4,i), c10i=__shfl_sync(FULL,m5,i);
            float c11r=__shfl_sync(FULL,m6,i), c11i=__shfl_sync(FULL,m7,i);
            const int lb  = 4 - i;
            const int msk = 1 << lb;
            const bool hi = (l >> lb) & 1;
            // uniform update: n = alpha*own + beta*partner
            const float aR = hi ? c11r : c00r, aI = hi ? c11i : c00i;
            const float bR = hi ? c10r : c01r, bI = hi ? c10i : c01i;
#pragma unroll
            for (int j = 0; j < 32; j++){
                float pr = __shfl_xor_sync(FULL, sr[j], msk);
                float pi = __shfl_xor_sync(FULL, si[j], msk);
                float orr = sr[j], oii = si[j];
                sr[j] = aR*orr - aI*oii + bR*pr - bI*pi;
                si[j] = aR*oii + aI*orr + bR*pi + bI*pr;
            }
        }

        // ---- wires 5..9: in-register butterflies (slot bit 9-i) ----
        {
            float c[8];
#define BCAST(i_) do{ c[0]=__shfl_sync(FULL,m0,i_); c[1]=__shfl_sync(FULL,m1,i_); \
    c[2]=__shfl_sync(FULL,m2,i_); c[3]=__shfl_sync(FULL,m3,i_); \
    c[4]=__shfl_sync(FULL,m4,i_); c[5]=__shfl_sync(FULL,m5,i_); \
    c[6]=__shfl_sync(FULL,m6,i_); c[7]=__shfl_sync(FULL,m7,i_);}while(0)
            BCAST(5); gate_in<4>(sr, si, c[0],c[1],c[2],c[3],c[4],c[5],c[6],c[7]);
            BCAST(6); gate_in<3>(sr, si, c[0],c[1],c[2],c[3],c[4],c[5],c[6],c[7]);
            BCAST(7); gate_in<2>(sr, si, c[0],c[1],c[2],c[3],c[4],c[5],c[6],c[7]);
            BCAST(8); gate_in<1>(sr, si, c[0],c[1],c[2],c[3],c[4],c[5],c[6],c[7]);
            BCAST(9); gate_in<0>(sr, si, c[0],c[1],c[2],c[3],c[4],c[5],c[6],c[7]);
#undef BCAST
        }

        // ---- CNOT-ring permutation (rounds 0..3), via padded SMEM ----
        if (r < 4){
            // re pass
#pragma unroll
            for (int j = 0; j < 32; j++) buf[l * 33 + j] = sr[j];
            __syncwarp();
#pragma unroll
            for (int j = 0; j < 32; j++){
                int y = l * 32 + j;
                int z = y;
#pragma unroll
                for (int k = 9; k >= 0; --k){
                    int cb  = 9 - k;
                    int tb2 = 9 - ((k + 1) % 10);
                    z ^= ((z >> cb) & 1) << tb2;
                }
                sr[j] = buf[(z >> 5) * 33 + (z & 31)];
            }
            __syncwarp();
            // im pass
#pragma unroll
            for (int j = 0; j < 32; j++) buf[l * 33 + j] = si[j];
            __syncwarp();
#pragma unroll
            for (int j = 0; j < 32; j++){
                int y = l * 32 + j;
                int z = y;
#pragma unroll
                for (int k = 9; k >= 0; --k){
                    int cb  = 9 - k;
                    int tb2 = 9 - ((k + 1) % 10);
                    z ^= ((z >> cb) & 1) << tb2;
                }
                si[j] = buf[(z >> 5) * 33 + (z & 31)];
            }
            __syncwarp();
        }
    }

    // ---- probabilities -> bf16 hi/lo, coalesced store via SMEM bounce ----
#pragma unroll
    for (int j = 0; j < 32; j++)
        buf[l * 33 + j] = sr[j] * sr[j] + si[j] * si[j];
    __syncwarp();
    const size_t o = (size_t)b * GQ + (size_t)g * QD;
#pragma unroll
    for (int j = 0; j < 32; j++){
        float p = buf[j * 33 + l];
        __nv_bfloat16 h = __float2bfloat16(p);
        ph[o + j * 32 + l] = h;
        pl[o + j * 32 + l] = __float2bfloat16(p - __bfloat162float(h));
    }
}

// ---------------- launch ----------------
extern "C" void kernel_launch(void* const* d_in, const int* in_sizes, int n_in,
                              void* d_out, int out_size)
{
    const float* x          = (const float*)d_in[0];
    const float* inp_scale  = (const float*)d_in[1];
    const float* proj_in_w  = (const float*)d_in[2];
    const float* proj_in_b  = (const float*)d_in[3];
    const float* reup_w     = (const float*)d_in[4];
    const float* reup_b     = (const float*)d_in[5];
    const float* q_weights  = (const float*)d_in[6];
    const float* upload_sc  = (const float*)d_in[7];
    const float* meas_w     = (const float*)d_in[8];
    const float* proj_out_w = (const float*)d_in[9];
    const float* proj_out_b = (const float*)d_in[10];
    float* out = (float*)d_out;

    void *pxq, *pang, *pph, *ppl, *pxh, *pxl, *pwih, *pwil, *pwoh, *pwol;
    cudaGetSymbolAddress(&pxq,  g_xq);
    cudaGetSymbolAddress(&pang, g_ang);
    cudaGetSymbolAddress(&pph,  g_ph);
    cudaGetSymbolAddress(&ppl,  g_pl);
    cudaGetSymbolAddress(&pxh,  g_xh);
    cudaGetSymbolAddress(&pxl,  g_xl);
    cudaGetSymbolAddress(&pwih, g_wih);
    cudaGetSymbolAddress(&pwil, g_wil);
    cudaGetSymbolAddress(&pwoh, g_woh);
    cudaGetSymbolAddress(&pwol, g_wol);

    // dynamic SMEM: BN=128 -> 81920; BN=64 -> 61440
    cudaFuncSetAttribute(mma_gemm<128>, cudaFuncAttributeMaxDynamicSharedMemorySize, 81920);
    cudaFuncSetAttribute(mma_gemm<64>,  cudaFuncAttributeMaxDynamicSharedMemorySize, 61440);

    // bf16 hi/lo splits
    split_bf16<<<(Bsz*INd + 255)/256, 256>>>(x, inp_scale,
        (__nv_bfloat16*)pxh, (__nv_bfloat16*)pxl, Bsz*INd);
    split_bf16<<<(GQ*INd + 255)/256, 256>>>(proj_in_w, nullptr,
        (__nv_bfloat16*)pwih, (__nv_bfloat16*)pwil, GQ*INd);
    split_bf16<<<(OUTd*GQ + 255)/256, 256>>>(proj_out_w, nullptr,
        (__nv_bfloat16*)pwoh, (__nv_bfloat16*)pwol, OUTd*GQ);

    // GEMM-in: xq[1024, 4096] = (x*scale) @ proj_in_w^T + b
    {
        dim3 grid(GQ/128, Bsz/128);
        mma_gemm<128><<<grid, 256, 81920>>>(Bsz, GQ, INd,
            (const __nv_bfloat16*)pxh, (const __nv_bfloat16*)pxl,
            (const __nv_bfloat16*)pwih, (const __nv_bfloat16*)pwil,
            proj_in_b, (float*)pxq);
    }

    // angles
    angles_kernel<<<Bsz, 320>>>(x, inp_scale, reup_w, reup_b, (float*)pang);

    // quantum circuit: 4096 states, one warp each -> probs (bf16 hi/lo)
    quantum_reg<<<1024, 128>>>((const float*)pxq, (const float*)pang,
        q_weights, upload_sc, meas_w,
        (__nv_bfloat16*)pph, (__nv_bfloat16*)ppl);

    // GEMM-out: out[1024, 1024] = probs @ proj_out_w^T + b
    {
        dim3 grid(OUTd/64, Bsz/128);
        mma_gemm<64><<<grid, 256, 61440>>>(Bsz, OUTd, GQ,
            (const __nv_bfloat16*)pph, (const __nv_bfloat16*)ppl,
            (const __nv_bfloat16*)pwoh, (const __nv_bfloat16*)pwol,
            proj_out_b, out);
    }
}